// round 15
// baseline (speedup 1.0000x reference)
#include <cuda_runtime.h>
#include <cmath>

#define TT   120
#define DD   64
#define DHH  32
#define NHH  2
#define DFF_ 128
#define DOUT_ 31
#define SCALE_ 0.17677669529663687f   // 1/sqrt(32)

// scratch (device globals: no allocation allowed)
__device__ float g_cross[TT * DD];
__device__ float g_h1[TT * DD];

// ---------------------------------------------------------------------------
// LayerNorm over 64 smem values, in place. All threads of block must call.
// ---------------------------------------------------------------------------
__device__ __forceinline__ void ln64_inplace(float* x, const float* g,
                                             const float* b, int tid,
                                             float* red) {
    __syncthreads();
    if (tid < 32) {
        float a = x[tid], c = x[tid + 32];
        float s = a + c, q = a * a + c * c;
#pragma unroll
        for (int o = 16; o; o >>= 1) {
            s += __shfl_xor_sync(0xffffffffu, s, o);
            q += __shfl_xor_sync(0xffffffffu, q, o);
        }
        if (tid == 0) {
            float m = s * (1.f / 64.f);
            red[0] = m;
            red[1] = rsqrtf(q * (1.f / 64.f) - m * m + 1e-5f);
        }
    }
    __syncthreads();
    if (tid < 64) x[tid] = (x[tid] - red[0]) * red[1] * g[tid] + b[tid];
    __syncthreads();
}

// ---------------------------------------------------------------------------
// Kernel 1: per-row  mem_t = audio[t] @ W_audio^T + b_audio  (64 x 1024 dot)
//           cross_t = (mem_t @ Wv2^T + bv2) @ Wo2^T + bo2
// 120 blocks x 256 threads (4 threads per output, shuffle reduce)
// ---------------------------------------------------------------------------
__global__ void k1_mem_cross(const float* __restrict__ audio,
                             const float* __restrict__ W_audio,
                             const float* __restrict__ b_audio,
                             const float* __restrict__ Wv2,
                             const float* __restrict__ bv2,
                             const float* __restrict__ Wo2,
                             const float* __restrict__ bo2) {
    int t = blockIdx.x;
    int tid = threadIdx.x;
    int o = tid >> 2, sgi = tid & 3;
    __shared__ float memv[64], tmp[64];

    const float4* a = (const float4*)(audio + t * 1024);
    const float4* w = (const float4*)(W_audio + o * 1024);
    float acc = 0.f;
    int base = sgi * 64;
#pragma unroll 8
    for (int j = 0; j < 64; j++) {
        float4 av = a[base + j], wv = w[base + j];
        acc += av.x * wv.x + av.y * wv.y + av.z * wv.z + av.w * wv.w;
    }
    acc += __shfl_xor_sync(0xffffffffu, acc, 1);
    acc += __shfl_xor_sync(0xffffffffu, acc, 2);
    if (sgi == 0) memv[o] = acc + b_audio[o];
    __syncthreads();

    float a2 = 0.f;
#pragma unroll
    for (int j = sgi; j < 64; j += 4) a2 += memv[j] * Wv2[o * 64 + j];
    a2 += __shfl_xor_sync(0xffffffffu, a2, 1);
    a2 += __shfl_xor_sync(0xffffffffu, a2, 2);
    if (sgi == 0) tmp[o] = a2 + bv2[o];
    __syncthreads();

    float a3 = 0.f;
#pragma unroll
    for (int j = sgi; j < 64; j += 4) a3 += tmp[j] * Wo2[o * 64 + j];
    a3 += __shfl_xor_sync(0xffffffffu, a3, 1);
    a3 += __shfl_xor_sync(0xffffffffu, a3, 2);
    if (sgi == 0) g_cross[t * 64 + o] = a3 + bo2[o];
}

// ---------------------------------------------------------------------------
// Kernel 2: sequential 120-step recurrence. ONE block, 256 threads.
// All weights (transposed, padded rows to kill bank conflicts) + K/V caches
// live in shared memory. h1[t] is saved to global for kernel 3.
// ---------------------------------------------------------------------------
struct S2 {
    float WqT[64 * 65];
    float WkT[64 * 65];
    float WvT[64 * 65];
    float WoT[64 * 65];
    float W1T[64 * 129];   // [in j<64][out i<128]
    float W2T[128 * 65];   // [in j<128][out i<64]
    float WrT[64 * 33];    // [in j<64][out i<31]
    float WmT[31 * 65];    // [in j<31][out i<64]
    float kcT[64 * 128];   // [dim][time]  (time padded to 128)
    float vc[120 * 65];    // [time][dim]  (dim padded to 65)
    float pe[10 * 64];
    float bq[64], bk[64], bv[64], bo[64];
    float c1[128], c2[64];
    float br[32], bm[64];
    float g1[64], be1[64], g2[64], be2[64], g3[64], be3[64];
    float cl[64], style[64];
    float cur[64], xq[64], q[64];
    float sc[2 * 128];
    float sa[64], h1[64], h2[64], u[128], h3[64], r[32];
    float red[2];
    float inv2[2];
};

__global__ void __launch_bounds__(256, 1)
k2_seq(const float* __restrict__ Wq, const float* __restrict__ bq,
       const float* __restrict__ Wk, const float* __restrict__ bk,
       const float* __restrict__ Wv, const float* __restrict__ bv,
       const float* __restrict__ Wo, const float* __restrict__ bo,
       const float* __restrict__ g1, const float* __restrict__ be1,
       const float* __restrict__ g2, const float* __restrict__ be2,
       const float* __restrict__ g3, const float* __restrict__ be3,
       const float* __restrict__ W1, const float* __restrict__ c1,
       const float* __restrict__ W2, const float* __restrict__ c2,
       const float* __restrict__ Wr, const float* __restrict__ br,
       const float* __restrict__ Wm, const float* __restrict__ bm,
       const float* __restrict__ obj_W) {
    extern __shared__ char raw[];
    S2& s = *reinterpret_cast<S2*>(raw);
    int tid = threadIdx.x;

    // ---- load weights (transposed) ----
    for (int idx = tid; idx < 4096; idx += 256) {
        int i = idx >> 6, j = idx & 63;
        s.WqT[j * 65 + i] = Wq[idx];
        s.WkT[j * 65 + i] = Wk[idx];
        s.WvT[j * 65 + i] = Wv[idx];
        s.WoT[j * 65 + i] = Wo[idx];
    }
    for (int idx = tid; idx < 8192; idx += 256) {       // W1 is (128,64)
        int i = idx >> 6, j = idx & 63;
        s.W1T[j * 129 + i] = W1[idx];
    }
    for (int idx = tid; idx < 8192; idx += 256) {       // W2 is (64,128)
        int i = idx >> 7, j = idx & 127;
        s.W2T[j * 65 + i] = W2[idx];
    }
    for (int idx = tid; idx < 31 * 64; idx += 256) {    // Wr is (31,64)
        int i = idx >> 6, j = idx & 63;
        s.WrT[j * 33 + i] = Wr[idx];
    }
    for (int idx = tid; idx < 64 * 31; idx += 256) {    // Wm is (64,31)
        int i = idx / 31, j = idx % 31;
        s.WmT[j * 65 + i] = Wm[idx];
    }
    if (tid < 64) {
        s.bq[tid] = bq[tid]; s.bk[tid] = bk[tid];
        s.bv[tid] = bv[tid]; s.bo[tid] = bo[tid];
        s.c2[tid] = c2[tid]; s.bm[tid] = bm[tid];
        s.g1[tid] = g1[tid]; s.be1[tid] = be1[tid];
        s.g2[tid] = g2[tid]; s.be2[tid] = be2[tid];
        s.g3[tid] = g3[tid]; s.be3[tid] = be3[tid];
        s.cl[tid] = g_cross[(TT - 1) * 64 + tid];
        float st = obj_W[tid * 5];          // obj_W[:,0], shape (64,5)
        s.style[tid] = st;
        s.cur[tid] = st;                    // emb[0] = style
    }
    if (tid < 128) s.c1[tid] = c1[tid];
    if (tid < 31) s.br[tid] = br[tid];
    // positional encoding (period 10, interleaved sin/cos)
    for (int idx = tid; idx < 640; idx += 256) {
        int p = idx >> 6, d = idx & 63;
        int i = d >> 1;
        float div = expf(-(float)(2 * i) * (9.210340371976184f / 64.f));
        float arg = (float)p * div;
        s.pe[idx] = (d & 1) ? cosf(arg) : sinf(arg);
    }
    __syncthreads();

    const float slopes[2] = {0.0625f, 0.00390625f};

    for (int t = 0; t < TT; t++) {
        // xq = emb[t] + pe[t % 10]
        if (tid < 64) s.xq[tid] = s.cur[tid] + s.pe[(t % 10) * 64 + tid];
        __syncthreads();

        // q / k_t / v_t  (192 outputs, one thread each, 64-term dot)
        if (tid < 192) {
            int which = tid >> 6, i = tid & 63;
            const float* WT = (which == 0) ? s.WqT : (which == 1) ? s.WkT : s.WvT;
            float acc = 0.f;
#pragma unroll
            for (int j = 0; j < 64; j++) acc += s.xq[j] * WT[j * 65 + i];
            if (which == 0)      s.q[i] = acc + s.bq[i];
            else if (which == 1) s.kcT[i * 128 + t] = acc + s.bk[i];
            else                 s.vc[t * 65 + i] = acc + s.bv[i];
        }
        __syncthreads();

        // attention scores: s[h][j] = (q_h . k_j,h)*SCALE - slope_h*((t-j)/10)
        int n = t + 1;
        if (tid < 2 * n) {
            int h = (tid >= n) ? 1 : 0;
            int j = tid - h * n;
            float acc = 0.f;
#pragma unroll
            for (int d = 0; d < 32; d++)
                acc += s.q[h * 32 + d] * s.kcT[(h * 32 + d) * 128 + j];
            s.sc[h * 128 + j] = acc * SCALE_ - slopes[h] * (float)((t - j) / 10);
        }
        __syncthreads();

        // softmax per head: warp 0 -> head 0, warp 1 -> head 1
        {
            int w = tid >> 5, lane = tid & 31;
            if (w < 2) {
                float m = -1e30f;
                for (int j = lane; j < n; j += 32) m = fmaxf(m, s.sc[w * 128 + j]);
#pragma unroll
                for (int o = 16; o; o >>= 1) m = fmaxf(m, __shfl_xor_sync(0xffffffffu, m, o));
                float ssum = 0.f;
                for (int j = lane; j < n; j += 32) {
                    float e = expf(s.sc[w * 128 + j] - m);
                    s.sc[w * 128 + j] = e;
                    ssum += e;
                }
#pragma unroll
                for (int o = 16; o; o >>= 1) ssum += __shfl_xor_sync(0xffffffffu, ssum, o);
                if (lane == 0) s.inv2[w] = 1.f / ssum;
            }
        }
        __syncthreads();

        // sa[o] = sum_j p[h][j] * v[j][o]   (split-4 over j within warp)
        {
            int o = tid >> 2, sgi = tid & 3;
            int h = o >> 5;
            float acc = 0.f;
            for (int j = sgi; j < n; j += 4) acc += s.sc[h * 128 + j] * s.vc[j * 65 + o];
            acc += __shfl_xor_sync(0xffffffffu, acc, 1);
            acc += __shfl_xor_sync(0xffffffffu, acc, 2);
            if (sgi == 0) s.sa[o] = acc * s.inv2[h];
        }
        __syncthreads();

        // out proj + residual  ->  h1 pre-LN
        {
            int o = tid >> 2, sgi = tid & 3;
            float acc = 0.f;
#pragma unroll
            for (int j = sgi; j < 64; j += 4) acc += s.sa[j] * s.WoT[j * 65 + o];
            acc += __shfl_xor_sync(0xffffffffu, acc, 1);
            acc += __shfl_xor_sync(0xffffffffu, acc, 2);
            if (sgi == 0) s.h1[o] = s.xq[o] + acc + s.bo[o];
        }
        ln64_inplace(s.h1, s.g1, s.be1, tid, s.red);

        // persist h1 (kernel 3 computes the real output using cross[t])
        if (tid < 64) g_h1[t * 64 + tid] = s.h1[tid];
        if (t == TT - 1) break;   // last row: only h1 is needed

        // h2 = LN(h1 + cross_last)
        if (tid < 64) s.h2[tid] = s.h1[tid] + s.cl[tid];
        ln64_inplace(s.h2, s.g2, s.be2, tid, s.red);

        // FFN up:  u = relu(h2 @ W1^T + c1)  (128 outputs, split-2)
        {
            int o = tid >> 1, sgi = tid & 1;
            float acc = 0.f;
#pragma unroll
            for (int j = sgi; j < 64; j += 2) acc += s.h2[j] * s.W1T[j * 129 + o];
            acc += __shfl_xor_sync(0xffffffffu, acc, 1);
            if (sgi == 0) s.u[o] = fmaxf(acc + s.c1[o], 0.f);
        }
        __syncthreads();

        // FFN down + residual -> h3 pre-LN  (64 outputs, split-4 over 128)
        {
            int o = tid >> 2, sgi = tid & 3;
            float acc = 0.f;
#pragma unroll
            for (int j = sgi; j < 128; j += 4) acc += s.u[j] * s.W2T[j * 65 + o];
            acc += __shfl_xor_sync(0xffffffffu, acc, 1);
            acc += __shfl_xor_sync(0xffffffffu, acc, 2);
            if (sgi == 0) s.h3[o] = s.h2[o] + acc + s.c2[o];
        }
        ln64_inplace(s.h3, s.g3, s.be3, tid, s.red);

        // r = h3 @ Wr^T + br  (31 outputs, split-4)
        {
            int o = tid >> 2, sgi = tid & 3;
            if (o < 32) {
                float acc = 0.f;
#pragma unroll
                for (int j = sgi; j < 64; j += 4) acc += s.h3[j] * s.WrT[j * 33 + o];
                acc += __shfl_xor_sync(0xffffffffu, acc, 1);
                acc += __shfl_xor_sync(0xffffffffu, acc, 2);
                if (sgi == 0 && o < 31) s.r[o] = acc + s.br[o];
            }
        }
        __syncthreads();

        // emb[t+1] = r @ Wm^T + bm + style  (64 outputs, split-4 over 31)
        {
            int o = tid >> 2, sgi = tid & 3;
            float acc = 0.f;
            for (int j = sgi; j < 31; j += 4) acc += s.r[j] * s.WmT[j * 65 + o];
            acc += __shfl_xor_sync(0xffffffffu, acc, 1);
            acc += __shfl_xor_sync(0xffffffffu, acc, 2);
            if (sgi == 0) s.cur[o] = acc + s.bm[o] + s.style[o];
        }
        __syncthreads();
    }
}

// ---------------------------------------------------------------------------
// Kernel 3: per-row output tail (uses per-row cross[t], unlike the loop)
//   h2 = LN(h1[t] + cross[t]); h3 = LN(h2 + FFN(h2)); out = h3 @ Wr^T + br
// 120 blocks x 128 threads
// ---------------------------------------------------------------------------
__global__ void k3_out(const float* __restrict__ W1, const float* __restrict__ c1,
                       const float* __restrict__ W2, const float* __restrict__ c2,
                       const float* __restrict__ Wr, const float* __restrict__ br,
                       const float* __restrict__ g2, const float* __restrict__ be2,
                       const float* __restrict__ g3, const float* __restrict__ be3,
                       float* __restrict__ out) {
    int t = blockIdx.x, tid = threadIdx.x;
    __shared__ float h2[64], u[128], h3[64], red[2];

    if (tid < 64) h2[tid] = g_h1[t * 64 + tid] + g_cross[t * 64 + tid];
    ln64_inplace(h2, g2, be2, tid, red);

    float acc = c1[tid];
#pragma unroll 8
    for (int j = 0; j < 64; j++) acc += h2[j] * W1[tid * 64 + j];
    u[tid] = fmaxf(acc, 0.f);
    __syncthreads();

    if (tid < 64) {
        float a2 = c2[tid];
#pragma unroll 8
        for (int j = 0; j < 128; j++) a2 += u[j] * W2[tid * 128 + j];
        h3[tid] = h2[tid] + a2;
    }
    ln64_inplace(h3, g3, be3, tid, red);

    if (tid < 31) {
        float a3 = br[tid];
#pragma unroll 8
        for (int j = 0; j < 64; j++) a3 += h3[j] * Wr[tid * 64 + j];
        out[t * 31 + tid] = a3;
    }
}

// ---------------------------------------------------------------------------
extern "C" void kernel_launch(void* const* d_in, const int* in_sizes, int n_in,
                              void* d_out, int out_size) {
    const float* audio   = (const float*)d_in[0];
    const float* W_audio = (const float*)d_in[1];
    const float* b_audio = (const float*)d_in[2];
    const float* obj_W   = (const float*)d_in[3];
    const float* Wq = (const float*)d_in[4];  const float* bq = (const float*)d_in[5];
    const float* Wk = (const float*)d_in[6];  const float* bk = (const float*)d_in[7];
    const float* Wv = (const float*)d_in[8];  const float* bv = (const float*)d_in[9];
    const float* Wo = (const float*)d_in[10]; const float* bo = (const float*)d_in[11];
    const float* Wv2 = (const float*)d_in[12]; const float* bv2 = (const float*)d_in[13];
    const float* Wo2 = (const float*)d_in[14]; const float* bo2 = (const float*)d_in[15];
    const float* g1 = (const float*)d_in[16]; const float* be1 = (const float*)d_in[17];
    const float* g2 = (const float*)d_in[18]; const float* be2 = (const float*)d_in[19];
    const float* g3 = (const float*)d_in[20]; const float* be3 = (const float*)d_in[21];
    const float* W1 = (const float*)d_in[22]; const float* c1 = (const float*)d_in[23];
    const float* W2 = (const float*)d_in[24]; const float* c2 = (const float*)d_in[25];
    const float* Wr = (const float*)d_in[26]; const float* br = (const float*)d_in[27];
    const float* Wm = (const float*)d_in[28]; const float* bm = (const float*)d_in[29];
    float* out = (float*)d_out;

    cudaFuncSetAttribute(k2_seq, cudaFuncAttributeMaxDynamicSharedMemorySize,
                         (int)sizeof(S2));

    k1_mem_cross<<<TT, 256>>>(audio, W_audio, b_audio, Wv2, bv2, Wo2, bo2);
    k2_seq<<<1, 256, sizeof(S2)>>>(Wq, bq, Wk, bk, Wv, bv, Wo, bo,
                                   g1, be1, g2, be2, g3, be3,
                                   W1, c1, W2, c2, Wr, br, Wm, bm, obj_W);
    k3_out<<<TT, 128>>>(W1, c1, W2, c2, Wr, br, g2, be2, g3, be3, out);
}

// round 16
// speedup vs baseline: 2.6998x; 2.6998x over previous
#include <cuda_runtime.h>
#include <cmath>

#define TT   120
#define DD   64
#define SCALE_ 0.17677669529663687f   // 1/sqrt(32)

// device scratch (no allocation allowed)
__device__ float g_cross[TT * DD];
__device__ float g_h1[TT * DD];
__device__ float g_WmrT[64 * 72];   // (Wm@Wr) transposed, padded: [j][o] at j*72+o
__device__ float g_cvec[64];        // Wm@br + bm + style

// ---------------------------------------------------------------------------
// LayerNorm over 64 smem values, in place (used by k3).
// ---------------------------------------------------------------------------
__device__ __forceinline__ void ln64_inplace(float* x, const float* g,
                                             const float* b, int tid,
                                             float* red) {
    __syncthreads();
    if (tid < 32) {
        float a = x[tid], c = x[tid + 32];
        float s = a + c, q = a * a + c * c;
#pragma unroll
        for (int o = 16; o; o >>= 1) {
            s += __shfl_xor_sync(0xffffffffu, s, o);
            q += __shfl_xor_sync(0xffffffffu, q, o);
        }
        if (tid == 0) {
            float m = s * (1.f / 64.f);
            red[0] = m;
            red[1] = rsqrtf(q * (1.f / 64.f) - m * m + 1e-5f);
        }
    }
    __syncthreads();
    if (tid < 64) x[tid] = (x[tid] - red[0]) * red[1] * g[tid] + b[tid];
    __syncthreads();
}

// ---------------------------------------------------------------------------
// Kernel 1: blocks 0..119: mem_t = audio[t]@W_audio^T+b ; cross_t = FFN2(mem_t)
//           block 120:     WmrT = (Wm@Wr)^T (padded), cvec = Wm@br+bm+style
// ---------------------------------------------------------------------------
__global__ void k1_mem_cross(const float* __restrict__ audio,
                             const float* __restrict__ W_audio,
                             const float* __restrict__ b_audio,
                             const float* __restrict__ Wv2,
                             const float* __restrict__ bv2,
                             const float* __restrict__ Wo2,
                             const float* __restrict__ bo2,
                             const float* __restrict__ Wr,
                             const float* __restrict__ br,
                             const float* __restrict__ Wm,
                             const float* __restrict__ bm,
                             const float* __restrict__ obj_W) {
    int tid = threadIdx.x;
    if (blockIdx.x == TT) {
        // ---- Wmr + cvec block ----
        __shared__ float swr[31 * 64], swm[64 * 31];
        for (int idx = tid; idx < 31 * 64; idx += 256) {
            swr[idx] = Wr[idx];
            swm[idx] = Wm[idx];
        }
        __syncthreads();
#pragma unroll
        for (int e = 0; e < 16; e++) {
            int idx = tid * 16 + e;
            int o = idx >> 6, j = idx & 63;
            float acc = 0.f;
#pragma unroll
            for (int i = 0; i < 31; i++) acc += swm[o * 31 + i] * swr[i * 64 + j];
            g_WmrT[j * 72 + o] = acc;
        }
        if (tid < 64) {
            float cv = bm[tid] + obj_W[tid * 5];
#pragma unroll
            for (int i = 0; i < 31; i++) cv += br[i] * swm[tid * 31 + i];
            g_cvec[tid] = cv;
        }
        return;
    }

    int t = blockIdx.x;
    int o = tid >> 2, sgi = tid & 3;
    __shared__ float arow[1024];
    __shared__ float memv[64], tmp[64];

    ((float4*)arow)[tid] = ((const float4*)(audio + t * 1024))[tid];
    __syncthreads();

    const float4* w4 = (const float4*)(W_audio + o * 1024) + sgi * 64;
    const float4* a4 = ((const float4*)arow) + sgi * 64;
    float a0 = 0.f, a1 = 0.f, a2 = 0.f, a3 = 0.f;
#pragma unroll 8
    for (int jj = 0; jj < 64; jj++) {
        float4 wv = w4[jj], av = a4[jj];
        a0 += wv.x * av.x; a1 += wv.y * av.y;
        a2 += wv.z * av.z; a3 += wv.w * av.w;
    }
    float acc = (a0 + a1) + (a2 + a3);
    acc += __shfl_xor_sync(0xffffffffu, acc, 1);
    acc += __shfl_xor_sync(0xffffffffu, acc, 2);
    if (sgi == 0) memv[o] = acc + b_audio[o];
    __syncthreads();

    float b0 = 0.f, b1 = 0.f;
#pragma unroll
    for (int j = sgi; j < 64; j += 8) b0 += memv[j] * Wv2[o * 64 + j];
#pragma unroll
    for (int j = sgi + 4; j < 64; j += 8) b1 += memv[j] * Wv2[o * 64 + j];
    float a2s = b0 + b1;
    a2s += __shfl_xor_sync(0xffffffffu, a2s, 1);
    a2s += __shfl_xor_sync(0xffffffffu, a2s, 2);
    if (sgi == 0) tmp[o] = a2s + bv2[o];
    __syncthreads();

    float c0 = 0.f, c1v = 0.f;
#pragma unroll
    for (int j = sgi; j < 64; j += 8) c0 += tmp[j] * Wo2[o * 64 + j];
#pragma unroll
    for (int j = sgi + 4; j < 64; j += 8) c1v += tmp[j] * Wo2[o * 64 + j];
    float a3s = c0 + c1v;
    a3s += __shfl_xor_sync(0xffffffffu, a3s, 1);
    a3s += __shfl_xor_sync(0xffffffffu, a3s, 2);
    if (sgi == 0) g_cross[t * 64 + o] = a3s + bo2[o];
}

// ---------------------------------------------------------------------------
// Kernel 2: sequential recurrence. ONE block, 256 threads.
// Wq/Wk/Wv/Wo rows + W1 half-rows + W2 quarter-rows live in REGISTERS.
// ---------------------------------------------------------------------------
struct S2 {
    float kcT[64 * 129];   // k cache transposed [dim][time], pad 129
    float vc[120 * 72];    // v cache [time][dim], pad 72
    float WmrT[64 * 72];   // fused output->emb matrix, transposed, pad 72
    float pe[640];
    float sc[256];         // exp(scores) per head
    float xq[64], q[64], sa[64], h2[64], h3p[64], h3[64], u[128];
    float bq[64], bk[64], bv[64], bo[64];
    float c1[128], c2[64];
    float g1[64], be1[64], g2[64], be2[64], g3[64], be3[64];
    float cl[64], cvec[64];
    float redE[8], red8[16], inv[4];
};

__global__ void __launch_bounds__(256, 1)
k2_seq(const float* __restrict__ Wq, const float* __restrict__ bq,
       const float* __restrict__ Wk, const float* __restrict__ bk,
       const float* __restrict__ Wv, const float* __restrict__ bv,
       const float* __restrict__ Wo, const float* __restrict__ bo,
       const float* __restrict__ g1, const float* __restrict__ be1,
       const float* __restrict__ g2, const float* __restrict__ be2,
       const float* __restrict__ g3, const float* __restrict__ be3,
       const float* __restrict__ W1, const float* __restrict__ c1,
       const float* __restrict__ W2, const float* __restrict__ c2,
       const float* __restrict__ obj_W) {
    extern __shared__ char raw[];
    S2& s = *reinterpret_cast<S2*>(raw);
    int tid = threadIdx.x;

    // ---- register-resident weights ----
    float wrow[64];     // one row of Wq/Wk/Wv/Wo depending on tid
    float w1h[32];      // half row of W1
    float w2q[32];      // quarter row of W2
    {
        const float* wsrc = (tid < 64)  ? Wq + tid * 64
                          : (tid < 128) ? Wk + (tid - 64) * 64
                          : (tid < 192) ? Wv + (tid - 128) * 64
                                        : Wo + (tid - 192) * 64;
        const float4* w4 = (const float4*)wsrc;
#pragma unroll
        for (int jj = 0; jj < 16; jj++) {
            float4 v = w4[jj];
            wrow[4 * jj] = v.x; wrow[4 * jj + 1] = v.y;
            wrow[4 * jj + 2] = v.z; wrow[4 * jj + 3] = v.w;
        }
        const float4* w14 = (const float4*)(W1 + (tid >> 1) * 64 + (tid & 1) * 32);
#pragma unroll
        for (int jj = 0; jj < 8; jj++) {
            float4 v = w14[jj];
            w1h[4 * jj] = v.x; w1h[4 * jj + 1] = v.y;
            w1h[4 * jj + 2] = v.z; w1h[4 * jj + 3] = v.w;
        }
        const float4* w24 = (const float4*)(W2 + (tid >> 2) * 128 + (tid & 3) * 32);
#pragma unroll
        for (int jj = 0; jj < 8; jj++) {
            float4 v = w24[jj];
            w2q[4 * jj] = v.x; w2q[4 * jj + 1] = v.y;
            w2q[4 * jj + 2] = v.z; w2q[4 * jj + 3] = v.w;
        }
    }

    // ---- smem prologue ----
    for (int idx = tid; idx < 64 * 72; idx += 256) s.WmrT[idx] = g_WmrT[idx];
    if (tid < 64) {
        s.bq[tid] = bq[tid]; s.bk[tid] = bk[tid];
        s.bv[tid] = bv[tid]; s.bo[tid] = bo[tid];
        s.c2[tid] = c2[tid];
        s.g1[tid] = g1[tid]; s.be1[tid] = be1[tid];
        s.g2[tid] = g2[tid]; s.be2[tid] = be2[tid];
        s.g3[tid] = g3[tid]; s.be3[tid] = be3[tid];
        s.cl[tid] = g_cross[(TT - 1) * 64 + tid];
        s.cvec[tid] = g_cvec[tid];
    }
    if (tid < 128) s.c1[tid] = c1[tid];
    for (int idx = tid; idx < 640; idx += 256) {
        int p = idx >> 6, d = idx & 63;
        int i = d >> 1;
        float div = __expf(-(float)(2 * i) * (9.210340371976184f / 64.f));
        float arg = (float)p * div;
        s.pe[idx] = (d & 1) ? cosf(arg) : sinf(arg);
    }
    __syncthreads();
    if (tid < 64) s.xq[tid] = obj_W[tid * 5] + s.pe[tid];   // emb[0]=style, pe[0]
    __syncthreads();

    const int o4 = tid >> 2, sg4 = tid & 3;
    const int lane = tid & 31;

    for (int t = 0; t < TT; t++) {
        // ---- A: q / k_t / v_t (threads 0..191, register weights) ----
        if (tid < 192) {
            float a0 = 0.f, a1 = 0.f, a2 = 0.f, a3 = 0.f;
#pragma unroll
            for (int jj = 0; jj < 16; jj++) {
                float4 xv = ((const float4*)s.xq)[jj];
                a0 += wrow[4 * jj] * xv.x;     a1 += wrow[4 * jj + 1] * xv.y;
                a2 += wrow[4 * jj + 2] * xv.z; a3 += wrow[4 * jj + 3] * xv.w;
            }
            float acc = (a0 + a1) + (a2 + a3);
            int which = tid >> 6, i = tid & 63;
            if (which == 0)      s.q[i] = acc + s.bq[i];
            else if (which == 1) s.kcT[i * 129 + t] = acc + s.bk[i];
            else                 s.vc[t * 72 + i] = acc + s.bv[i];
        }
        __syncthreads();

        // ---- B: scores + exp (fused, no max pass; scores are O(1)) ----
        int n = t + 1;
        if (tid < 2 * n) {
            int h = (tid >= n) ? 1 : 0;
            int j = tid - h * n;
            float sl = h ? 0.00390625f : 0.0625f;
            float a0 = 0.f, a1 = 0.f, a2 = 0.f, a3 = 0.f;
            int kb = h * 32 * 129 + j;
#pragma unroll
            for (int dd = 0; dd < 8; dd++) {
                float4 qv = *(const float4*)&s.q[h * 32 + dd * 4];
                a0 += qv.x * s.kcT[kb + (dd * 4 + 0) * 129];
                a1 += qv.y * s.kcT[kb + (dd * 4 + 1) * 129];
                a2 += qv.z * s.kcT[kb + (dd * 4 + 2) * 129];
                a3 += qv.w * s.kcT[kb + (dd * 4 + 3) * 129];
            }
            float sc = ((a0 + a1) + (a2 + a3)) * SCALE_ - sl * (float)((t - j) / 10);
            s.sc[h * 128 + j] = __expf(sc);
        }
        __syncthreads();

        // ---- D: sa_un[o] = sum_j e[h][j]*v[j][o]; head sums piggybacked ----
        {
            int hb = (o4 >= 32) ? 128 : 0;
            float acc = 0.f, acc2 = 0.f, ps = 0.f, ps2 = 0.f;
            for (int j = sg4; j < n; j += 8) {
                float p = s.sc[hb + j];
                acc += p * s.vc[j * 72 + o4];
                ps += p;
            }
            for (int j = sg4 + 4; j < n; j += 8) {
                float p = s.sc[hb + j];
                acc2 += p * s.vc[j * 72 + o4];
                ps2 += p;
            }
            acc += acc2; ps += ps2;
            acc += __shfl_xor_sync(0xffffffffu, acc, 1);
            acc += __shfl_xor_sync(0xffffffffu, acc, 2);
            ps  += __shfl_xor_sync(0xffffffffu, ps, 1);
            ps  += __shfl_xor_sync(0xffffffffu, ps, 2);
            if (sg4 == 0) s.sa[o4] = acc;
            if (tid == 0)   s.inv[0] = __fdividef(1.f, ps);
            if (tid == 128) s.inv[1] = __fdividef(1.f, ps);
        }
        __syncthreads();

        // ---- E: Wo + norm-scale + residual + LN1 + store h1 + LN2 -> h2 ----
        if (tid >= 192) {
            int o = tid - 192;
            float inv0 = s.inv[0], inv1 = s.inv[1];
            float a0 = 0.f, a1 = 0.f, b0 = 0.f, b1 = 0.f;
#pragma unroll
            for (int jj = 0; jj < 8; jj++) {
                float4 xv = ((const float4*)s.sa)[jj];
                a0 += wrow[4 * jj] * xv.x;     a1 += wrow[4 * jj + 1] * xv.y;
                a0 += wrow[4 * jj + 2] * xv.z; a1 += wrow[4 * jj + 3] * xv.w;
            }
#pragma unroll
            for (int jj = 8; jj < 16; jj++) {
                float4 xv = ((const float4*)s.sa)[jj];
                b0 += wrow[4 * jj] * xv.x;     b1 += wrow[4 * jj + 1] * xv.y;
                b0 += wrow[4 * jj + 2] * xv.z; b1 += wrow[4 * jj + 3] * xv.w;
            }
            float h1p = s.xq[o] + (a0 + a1) * inv0 + (b0 + b1) * inv1 + s.bo[o];
            // LN1 across 64 threads (warps 6,7) via named barrier
            float sm = h1p, sq = h1p * h1p;
#pragma unroll
            for (int off = 16; off; off >>= 1) {
                sm += __shfl_xor_sync(0xffffffffu, sm, off);
                sq += __shfl_xor_sync(0xffffffffu, sq, off);
            }
            int w2i = (tid >> 5) - 6;
            if (lane == 0) { s.redE[w2i * 2] = sm; s.redE[w2i * 2 + 1] = sq; }
            asm volatile("bar.sync 1, 64;" ::: "memory");
            sm = s.redE[0] + s.redE[2]; sq = s.redE[1] + s.redE[3];
            float m = sm * (1.f / 64.f);
            float rs = rsqrtf(sq * (1.f / 64.f) - m * m + 1e-5f);
            float h1 = (h1p - m) * rs * s.g1[o] + s.be1[o];
            g_h1[t * 64 + o] = h1;
            float h2p = h1 + s.cl[o];
            float sm2 = h2p, sq2 = h2p * h2p;
#pragma unroll
            for (int off = 16; off; off >>= 1) {
                sm2 += __shfl_xor_sync(0xffffffffu, sm2, off);
                sq2 += __shfl_xor_sync(0xffffffffu, sq2, off);
            }
            if (lane == 0) { s.redE[4 + w2i * 2] = sm2; s.redE[5 + w2i * 2] = sq2; }
            asm volatile("bar.sync 1, 64;" ::: "memory");
            sm2 = s.redE[4] + s.redE[6]; sq2 = s.redE[5] + s.redE[7];
            float m2 = sm2 * (1.f / 64.f);
            float rs2 = rsqrtf(sq2 * (1.f / 64.f) - m2 * m2 + 1e-5f);
            s.h2[o] = (h2p - m2) * rs2 * s.g2[o] + s.be2[o];
        }
        __syncthreads();
        if (t == TT - 1) break;

        // ---- H: FFN up, u = relu(h2@W1^T+c1)  (pair split, register W1) ----
        {
            int half = tid & 1, row = tid >> 1;
            float a0 = 0.f, a1 = 0.f, a2 = 0.f, a3 = 0.f;
            const float4* h24 = (const float4*)(s.h2 + half * 32);
#pragma unroll
            for (int jj = 0; jj < 8; jj++) {
                float4 xv = h24[jj];
                a0 += w1h[4 * jj] * xv.x;     a1 += w1h[4 * jj + 1] * xv.y;
                a2 += w1h[4 * jj + 2] * xv.z; a3 += w1h[4 * jj + 3] * xv.w;
            }
            float acc = (a0 + a1) + (a2 + a3);
            acc += __shfl_xor_sync(0xffffffffu, acc, 1);
            if (half == 0) s.u[row] = fmaxf(acc + s.c1[row], 0.f);
        }
        __syncthreads();

        // ---- I: FFN down + residual -> h3p; LN3 warp partials ----
        {
            int row = o4;
            float a0 = 0.f, a1 = 0.f, a2 = 0.f, a3 = 0.f;
            const float4* u4 = (const float4*)(s.u + sg4 * 32);
#pragma unroll
            for (int jj = 0; jj < 8; jj++) {
                float4 xv = u4[jj];
                a0 += w2q[4 * jj] * xv.x;     a1 += w2q[4 * jj + 1] * xv.y;
                a2 += w2q[4 * jj + 2] * xv.z; a3 += w2q[4 * jj + 3] * xv.w;
            }
            float acc = (a0 + a1) + (a2 + a3);
            acc += __shfl_xor_sync(0xffffffffu, acc, 1);
            acc += __shfl_xor_sync(0xffffffffu, acc, 2);
            float h3pv = s.h2[row] + acc + s.c2[row];
            if (sg4 == 0) s.h3p[row] = h3pv;
            float vs = (sg4 == 0) ? h3pv : 0.f;
            float vq = (sg4 == 0) ? h3pv * h3pv : 0.f;
#pragma unroll
            for (int off = 4; off <= 16; off <<= 1) {
                vs += __shfl_xor_sync(0xffffffffu, vs, off);
                vq += __shfl_xor_sync(0xffffffffu, vq, off);
            }
            if (lane == 0) {
                int w = tid >> 5;
                s.red8[w * 2] = vs; s.red8[w * 2 + 1] = vq;
            }
        }
        __syncthreads();

        // ---- LN3 apply ----
        if (tid < 64) {
            float4 r0 = ((const float4*)s.red8)[0];
            float4 r1 = ((const float4*)s.red8)[1];
            float4 r2 = ((const float4*)s.red8)[2];
            float4 r3 = ((const float4*)s.red8)[3];
            float sm = (r0.x + r0.z) + (r1.x + r1.z) + (r2.x + r2.z) + (r3.x + r3.z);
            float sq = (r0.y + r0.w) + (r1.y + r1.w) + (r2.y + r2.w) + (r3.y + r3.w);
            float m = sm * (1.f / 64.f);
            float rs = rsqrtf(sq * (1.f / 64.f) - m * m + 1e-5f);
            s.h3[tid] = (s.h3p[tid] - m) * rs * s.g3[tid] + s.be3[tid];
        }
        __syncthreads();

        // ---- L: next emb + PE: xq' = h3 @ WmrT + cvec + pe[(t+1)%10] ----
        {
            float acc = 0.f, acc2 = 0.f;
#pragma unroll
            for (int j = sg4; j < 64; j += 8) acc += s.h3[j] * s.WmrT[j * 72 + o4];
#pragma unroll
            for (int j = sg4 + 4; j < 64; j += 8) acc2 += s.h3[j] * s.WmrT[j * 72 + o4];
            acc += acc2;
            acc += __shfl_xor_sync(0xffffffffu, acc, 1);
            acc += __shfl_xor_sync(0xffffffffu, acc, 2);
            if (sg4 == 0)
                s.xq[o4] = acc + s.cvec[o4] + s.pe[((t + 1) % 10) * 64 + o4];
        }
        __syncthreads();
    }
}

// ---------------------------------------------------------------------------
// Kernel 3: per-row output tail with per-row cross[t].
// ---------------------------------------------------------------------------
__global__ void k3_out(const float* __restrict__ W1, const float* __restrict__ c1,
                       const float* __restrict__ W2, const float* __restrict__ c2,
                       const float* __restrict__ Wr, const float* __restrict__ br,
                       const float* __restrict__ g2, const float* __restrict__ be2,
                       const float* __restrict__ g3, const float* __restrict__ be3,
                       float* __restrict__ out) {
    int t = blockIdx.x, tid = threadIdx.x;
    __shared__ float h2[64], u[128], h3[64], red[2];

    if (tid < 64) h2[tid] = g_h1[t * 64 + tid] + g_cross[t * 64 + tid];
    ln64_inplace(h2, g2, be2, tid, red);

    float a0 = 0.f, a1 = 0.f, a2 = 0.f, a3 = 0.f;
    const float4* w14 = (const float4*)(W1 + tid * 64);
#pragma unroll
    for (int jj = 0; jj < 16; jj++) {
        float4 wv = w14[jj];
        float4 xv = ((const float4*)h2)[jj];
        a0 += wv.x * xv.x; a1 += wv.y * xv.y; a2 += wv.z * xv.z; a3 += wv.w * xv.w;
    }
    u[tid] = fmaxf((a0 + a1) + (a2 + a3) + c1[tid], 0.f);
    __syncthreads();

    if (tid < 64) {
        float b0 = 0.f, b1 = 0.f, b2 = 0.f, b3 = 0.f;
        const float4* w24 = (const float4*)(W2 + tid * 128);
#pragma unroll
        for (int jj = 0; jj < 32; jj++) {
            float4 wv = w24[jj];
            float4 xv = ((const float4*)u)[jj];
            b0 += wv.x * xv.x; b1 += wv.y * xv.y; b2 += wv.z * xv.z; b3 += wv.w * xv.w;
        }
        h3[tid] = h2[tid] + (b0 + b1) + (b2 + b3) + c2[tid];
    }
    ln64_inplace(h3, g3, be3, tid, red);

    if (tid < 31) {
        float c0 = 0.f, c1a = 0.f, c2a = 0.f, c3a = 0.f;
        const float4* wr4 = (const float4*)(Wr + tid * 64);
#pragma unroll
        for (int jj = 0; jj < 16; jj++) {
            float4 wv = wr4[jj];
            float4 xv = ((const float4*)h3)[jj];
            c0 += wv.x * xv.x; c1a += wv.y * xv.y; c2a += wv.z * xv.z; c3a += wv.w * xv.w;
        }
        out[t * 31 + tid] = (c0 + c1a) + (c2a + c3a) + br[tid];
    }
}

// ---------------------------------------------------------------------------
extern "C" void kernel_launch(void* const* d_in, const int* in_sizes, int n_in,
                              void* d_out, int out_size) {
    const float* audio   = (const float*)d_in[0];
    const float* W_audio = (const float*)d_in[1];
    const float* b_audio = (const float*)d_in[2];
    const float* obj_W   = (const float*)d_in[3];
    const float* Wq = (const float*)d_in[4];  const float* bq = (const float*)d_in[5];
    const float* Wk = (const float*)d_in[6];  const float* bk = (const float*)d_in[7];
    const float* Wv = (const float*)d_in[8];  const float* bv = (const float*)d_in[9];
    const float* Wo = (const float*)d_in[10]; const float* bo = (const float*)d_in[11];
    const float* Wv2 = (const float*)d_in[12]; const float* bv2 = (const float*)d_in[13];
    const float* Wo2 = (const float*)d_in[14]; const float* bo2 = (const float*)d_in[15];
    const float* g1 = (const float*)d_in[16]; const float* be1 = (const float*)d_in[17];
    const float* g2 = (const float*)d_in[18]; const float* be2 = (const float*)d_in[19];
    const float* g3 = (const float*)d_in[20]; const float* be3 = (const float*)d_in[21];
    const float* W1 = (const float*)d_in[22]; const float* c1 = (const float*)d_in[23];
    const float* W2 = (const float*)d_in[24]; const float* c2 = (const float*)d_in[25];
    const float* Wr = (const float*)d_in[26]; const float* br = (const float*)d_in[27];
    const float* Wm = (const float*)d_in[28]; const float* bm = (const float*)d_in[29];
    float* out = (float*)d_out;

    cudaFuncSetAttribute(k2_seq, cudaFuncAttributeMaxDynamicSharedMemorySize,
                         (int)sizeof(S2));

    k1_mem_cross<<<TT + 1, 256>>>(audio, W_audio, b_audio, Wv2, bv2, Wo2, bo2,
                                  Wr, br, Wm, bm, obj_W);
    k2_seq<<<1, 256, sizeof(S2)>>>(Wq, bq, Wk, bk, Wv, bv, Wo, bo,
                                   g1, be1, g2, be2, g3, be3,
                                   W1, c1, W2, c2, obj_W);
    k3_out<<<TT, 128>>>(W1, c1, W2, c2, Wr, br, g2, be2, g3, be3, out);
}